// round 15
// baseline (speedup 1.0000x reference)
#include <cuda_runtime.h>

#define Nn   1024
#define Cc   64
#define HID  128
#define TS   16
#define NTS  (Nn / TS)                  // 64
#define NUNITS (NTS * (NTS + 1) / 2)    // 2080
#define PNCH 32

typedef unsigned long long u64;

__device__ float2 g_p  [HID * Nn];       // (Ei, Ej) interleaved
__device__ float2 g_eip[HID * Nn / 2];   // (Ei_n, Ei_{n+1}), n even
__device__ float2 g_ejp[HID * Nn / 2];   // (Ej_n, Ej_{n+1}), n even

__device__ __forceinline__ float rcp_mufu(float d) {
    float r; asm("rcp.approx.f32 %0, %1;" : "=f"(r) : "f"(d)); return r;
}
__device__ __forceinline__ u64 pack2(float lo, float hi) {
    u64 r; asm("mov.b64 %0, {%1, %2};" : "=l"(r) : "f"(lo), "f"(hi)); return r;
}
__device__ __forceinline__ void unpack2(u64 v, float& lo, float& hi) {
    asm("mov.b64 {%0, %1}, %2;" : "=f"(lo), "=f"(hi) : "l"(v));
}
__device__ __forceinline__ u64 fma2(u64 a, u64 b, u64 c) {
    u64 d; asm("fma.rn.f32x2 %0, %1, %2, %3;" : "=l"(d) : "l"(a), "l"(b), "l"(c)); return d;
}
__device__ __forceinline__ u64 mul2(u64 a, u64 b) {
    u64 d; asm("mul.rn.f32x2 %0, %1, %2;" : "=l"(d) : "l"(a), "l"(b)); return d;
}
__device__ __forceinline__ u64 add2(u64 a, u64 b) {
    u64 d; asm("add.rn.f32x2 %0, %1, %2;" : "=l"(d) : "l"(a), "l"(b)); return d;
}

#define ONE2  0x3F8000003F800000ULL
#define NEG12 0xBF800000BF800000ULL

// ---------------------------------------------------------------------------
// prep (R14, unchanged): GEMV + exp, emits interleaved + j-pair layouts.
// ---------------------------------------------------------------------------
__global__ __launch_bounds__(256) void prep_kernel(const float* __restrict__ x,
                                                   const float* __restrict__ W1,
                                                   const float* __restrict__ b1) {
    __shared__ float t_s[Cc][PNCH];
    const int n0   = blockIdx.x * PNCH;
    const int tid  = threadIdx.x;
    const int lane = tid & 31;
    const int w    = tid >> 5;

    for (int k = tid; k < Cc * PNCH; k += 256) {
        int c = k >> 5, n = k & 31;
        t_s[c][n] = tanhf(x[c * Nn + n0 + n]);
    }
    __syncthreads();

#pragma unroll
    for (int g = 0; g < 4; g++) {
        const int h = blockIdx.y * 32 + w * 4 + g;
        const float bb = b1[h];
        float acci = bb, accj = 0.0f;
#pragma unroll
        for (int c = 0; c < Cc; c++) {
            float wj = W1[h * (2 * Cc) + c];
            float wi = W1[h * (2 * Cc) + Cc + c];
            float t  = t_s[c][lane];
            accj = fmaf(wj, t, accj);
            acci = fmaf(wi, t, acci);
        }
        float Ei = fminf(expf(2.0f * acci), 1e8f);
        float Ej = fminf(expf(2.0f * accj), 1e8f);
        const int n = n0 + lane;
        g_p[h * Nn + n] = make_float2(Ei, Ej);
        float EiN = __shfl_down_sync(0xffffffffu, Ei, 1);
        float EjN = __shfl_down_sync(0xffffffffu, Ej, 1);
        if ((lane & 1) == 0) {
            g_eip[h * (Nn >> 1) + (n >> 1)] = make_float2(Ei, EiN);
            g_ejp[h * (Nn >> 1) + (n >> 1)] = make_float2(Ej, EjN);
        }
    }

    __threadfence();
    __syncthreads();
    asm volatile("griddepcontrol.launch_dependents;" ::: "memory");
}

// ---------------------------------------------------------------------------
// pair: 16x16 triangular unit. 256 threads = 4 h-groups x 64.
// Thread (g, ii, jq): 1 i x 4 j (two f32x2 packs) over 32 h.
//   A1 = Ei_i*Ej_j+1 ; B1 = Ei_j*Ej_i+1 ; D = A1*B1
//   acc += w2[h]*(D - A1 - B1)/D    [= w2*(tanh+tanh)/2]
//   out = 2*(accTot + b2)
// ---------------------------------------------------------------------------
__global__ __launch_bounds__(256) void pair_kernel(const float* __restrict__ W2,
                                                   const float* __restrict__ b2,
                                                   float* __restrict__ out) {
    __shared__ __align__(16) float2 iS [HID][TS];      // (Ei_i, Ej_i)  16KB
    __shared__ __align__(16) float2 bjS[HID][TS / 2];  // Ej j-pairs     8KB
    __shared__ __align__(16) float2 biS[HID][TS / 2];  // Ei j-pairs     8KB
    __shared__ __align__(8)  float2 w2d[HID];          // dup(w2)        1KB
    __shared__ float red[3][TS * TS];                  // partials       3KB

    int rem = blockIdx.x, a = 0, len = NTS;
    while (rem >= len) { rem -= len; a++; len--; }
    const int b  = a + rem;
    const int i0 = a * TS, j0 = b * TS;

    const int tid = threadIdx.x;
    if (tid < HID) { float w = W2[tid]; w2d[tid] = make_float2(w, w); }
    const float b2v = b2[0];

    asm volatile("griddepcontrol.wait;" ::: "memory");

    // stage: iS 1024 float4, bj/bi 512 float4 each
    for (int t = tid; t < 2048; t += 256) {
        if (t < 1024) {
            int h = t >> 3, c2 = (t & 7) * 2;
            *(float4*)&iS[h][c2] = *(const float4*)&g_p[h * Nn + i0 + c2];
        } else {
            int k   = t - 1024;
            int sel = k >> 9;                 // 0 = Ej pairs, 1 = Ei pairs
            int m   = k & 511;
            int h   = m >> 2, c2 = (m & 3) * 2;
            const float2* src = sel ? g_eip : g_ejp;
            float4 v = *(const float4*)&src[h * (Nn >> 1) + (j0 >> 1) + c2];
            if (sel) *(float4*)&biS[h][c2] = v;
            else     *(float4*)&bjS[h][c2] = v;
        }
    }
    __syncthreads();

    const int g  = tid >> 6;        // h-group 0..3 (32 h each)
    const int t2 = tid & 63;
    const int ii = t2 >> 2;         // 0..15
    const int jq = t2 & 3;          // 0..3 -> j = 4*jq .. 4*jq+3
    const int h0 = g * 32;

    u64 accA = 0, accB = 0;         // packed accs for (j0,j1) and (j2,j3)
#pragma unroll 8
    for (int hl = 0; hl < 32; hl++) {
        const int H = h0 + hl;
        float2 ai = iS[H][ii];
        u64 eid = pack2(ai.x, ai.x);
        u64 ejd = pack2(ai.y, ai.y);
        u64 wd  = *(const u64*)&w2d[H];
        // two adjacent j-pairs as one LDS.128 each
        float4 bjq = *(const float4*)&bjS[H][jq * 2];
        float4 biq = *(const float4*)&biS[H][jq * 2];
        u64 bjA = *(const u64*)&bjq.x, bjB = *(const u64*)&bjq.z;
        u64 biA = *(const u64*)&biq.x, biB = *(const u64*)&biq.z;

        // pack A (j0,j1)
        u64 A1 = fma2(eid, bjA, ONE2);
        u64 B1 = fma2(biA, ejd, ONE2);
        u64 D  = mul2(A1, B1);
        u64 S  = add2(A1, B1);
        u64 nu = fma2(S, NEG12, D);
        u64 wn = mul2(nu, wd);
        float d0, d1; unpack2(D, d0, d1);
        u64 rc = pack2(rcp_mufu(d0), rcp_mufu(d1));
        accA = fma2(wn, rc, accA);

        // pack B (j2,j3)
        u64 A1b = fma2(eid, bjB, ONE2);
        u64 B1b = fma2(biB, ejd, ONE2);
        u64 Db  = mul2(A1b, B1b);
        u64 Sb  = add2(A1b, B1b);
        u64 nub = fma2(Sb, NEG12, Db);
        u64 wnb = mul2(nub, wd);
        float e0, e1; unpack2(Db, e0, e1);
        u64 rcb = pack2(rcp_mufu(e0), rcp_mufu(e1));
        accB = fma2(wnb, rcb, accB);
    }

    float v0, v1, v2, v3;
    unpack2(accA, v0, v1);
    unpack2(accB, v2, v3);

    const int base = ii * TS + jq * 4;
    if (g > 0) {
        red[g - 1][base + 0] = v0;
        red[g - 1][base + 1] = v1;
        red[g - 1][base + 2] = v2;
        red[g - 1][base + 3] = v3;
    }
    __syncthreads();
    if (g == 0) {
        v0 += red[0][base + 0] + red[1][base + 0] + red[2][base + 0];
        v1 += red[0][base + 1] + red[1][base + 1] + red[2][base + 1];
        v2 += red[0][base + 2] + red[1][base + 2] + red[2][base + 2];
        v3 += red[0][base + 3] + red[1][base + 3] + red[2][base + 3];

        float4 o;
        o.x = 2.0f * (v0 + b2v);
        o.y = 2.0f * (v1 + b2v);
        o.z = 2.0f * (v2 + b2v);
        o.w = 2.0f * (v3 + b2v);

        const int gi = i0 + ii;
        const int gj = j0 + jq * 4;
        *(float4*)&out[gi * Nn + gj] = o;     // upper tile, coalesced
        out[(gj + 0) * Nn + gi] = o.x;        // mirror
        out[(gj + 1) * Nn + gi] = o.y;
        out[(gj + 2) * Nn + gi] = o.z;
        out[(gj + 3) * Nn + gi] = o.w;
    }
}

extern "C" void kernel_launch(void* const* d_in, const int* in_sizes, int n_in,
                              void* d_out, int out_size) {
    const float* x  = (const float*)d_in[0];
    const float* W1 = (const float*)d_in[1];
    const float* b1 = (const float*)d_in[2];
    const float* W2 = (const float*)d_in[3];
    const float* b2 = (const float*)d_in[4];
    float* out = (float*)d_out;

    prep_kernel<<<dim3(32, 4), 256>>>(x, W1, b1);

    cudaLaunchConfig_t cfg = {};
    cfg.gridDim  = dim3(NUNITS);
    cfg.blockDim = dim3(256);
    cfg.dynamicSmemBytes = 0;
    cfg.stream = 0;
    cudaLaunchAttribute attr[1];
    attr[0].id = cudaLaunchAttributeProgrammaticStreamSerialization;
    attr[0].val.programmaticStreamSerializationAllowed = 1;
    cfg.attrs = attr;
    cfg.numAttrs = 1;
    cudaLaunchKernelEx(&cfg, pair_kernel, W2, b2, (float*)out);
}

// round 16
// speedup vs baseline: 1.0007x; 1.0007x over previous
#include <cuda_runtime.h>

#define Nn   1024
#define Cc   64
#define HID  128
#define TS   16
#define NTS  (Nn / TS)                  // 64
#define NUNITS (NTS * (NTS + 1) / 2)    // 2080
#define PNCH 32

__device__ float2 g_p [HID * Nn];       // (Ei, Ej) interleaved (i-side)
__device__ float  g_ei[HID * Nn];       // Ei deinterleaved (j-side)
__device__ float  g_ej[HID * Nn];       // Ej deinterleaved (j-side)
__device__ float  g_sw2;                // sum of W2

__device__ __forceinline__ float rcp_mufu(float d) {
    float r; asm("rcp.approx.f32 %0, %1;" : "=f"(r) : "f"(d)); return r;
}

// ---------------------------------------------------------------------------
// prep: GEMV (precise tanhf) -> E = exp(2*p), clamped; emits interleaved
// i-side + deinterleaved j-side layouts; block(0,0) reduces sum(W2).
// ---------------------------------------------------------------------------
__global__ __launch_bounds__(256) void prep_kernel(const float* __restrict__ x,
                                                   const float* __restrict__ W1,
                                                   const float* __restrict__ b1,
                                                   const float* __restrict__ W2) {
    __shared__ float t_s[Cc][PNCH];
    const int n0   = blockIdx.x * PNCH;
    const int tid  = threadIdx.x;
    const int lane = tid & 31;
    const int w    = tid >> 5;

    for (int k = tid; k < Cc * PNCH; k += 256) {
        int c = k >> 5, n = k & 31;
        t_s[c][n] = tanhf(x[c * Nn + n0 + n]);
    }
    __syncthreads();

#pragma unroll
    for (int g = 0; g < 4; g++) {
        const int h = blockIdx.y * 32 + w * 4 + g;
        const float bb = b1[h];
        float acci = bb, accj = 0.0f;
#pragma unroll
        for (int c = 0; c < Cc; c++) {
            float wj = W1[h * (2 * Cc) + c];        // warp-uniform broadcast
            float wi = W1[h * (2 * Cc) + Cc + c];
            float t  = t_s[c][lane];
            accj = fmaf(wj, t, accj);
            acci = fmaf(wi, t, acci);
        }
        float Ei = fminf(expf(2.0f * acci), 1e8f);
        float Ej = fminf(expf(2.0f * accj), 1e8f);
        const int n = n0 + lane;
        g_p [h * Nn + n] = make_float2(Ei, Ej);
        g_ei[h * Nn + n] = Ei;
        g_ej[h * Nn + n] = Ej;
    }

    if (blockIdx.x == 0 && blockIdx.y == 0 && tid < 32) {
        float s = 0.0f;
        for (int k = lane; k < HID; k += 32) s += W2[k];
#pragma unroll
        for (int o = 16; o; o >>= 1) s += __shfl_xor_sync(0xffffffffu, s, o);
        if (lane == 0) g_sw2 = s;
    }

    __threadfence();
    __syncthreads();
    asm volatile("griddepcontrol.launch_dependents;" ::: "memory");
}

// ---------------------------------------------------------------------------
// pair: 16x16 triangular unit. 256 threads = 4 h-groups x 64 (16 i x 4 jq).
// Thread: 1 i x 4 j over 32 h. Per (h,j), one combined term:
//   A1 = Ei_i*Ej_j + 1 ; B1 = Ei_j*Ej_i + 1
//   tanh(pi_i+pj_j)+tanh(pi_j+pj_i) = 2 - 2*(A1+B1)/(A1*B1)
//   acc += w2[h]*(A1+B1)*rcp(A1*B1)
//   out[i,j] = out[j,i] = 2*(sumW2 + b2 - accTot)
// ---------------------------------------------------------------------------
__global__ __launch_bounds__(256, 6) void pair_kernel(const float* __restrict__ W2,
                                                      const float* __restrict__ b2,
                                                      float* __restrict__ out) {
    __shared__ __align__(16) float2 iS [HID][TS];   // (Ei_i, Ej_i)  16KB
    __shared__ __align__(16) float  bjS[HID][TS];   // Ej at j cols   8KB
    __shared__ __align__(16) float  biS[HID][TS];   // Ei at j cols   8KB
    __shared__ float w2s[HID];
    __shared__ float red[3][TS * TS];               // 3KB

    int rem = blockIdx.x, a = 0, len = NTS;
    while (rem >= len) { rem -= len; a++; len--; }
    const int b  = a + rem;
    const int i0 = a * TS, j0 = b * TS;

    const int tid = threadIdx.x;
    if (tid < HID) w2s[tid] = W2[tid];
    const float b2v = b2[0];

    asm volatile("griddepcontrol.wait;" ::: "memory");
    const float sw2 = g_sw2;

    // stage: iS 1024 float4; bjS 512 float4; biS 512 float4
    for (int t = tid; t < 2048; t += 256) {
        if (t < 1024) {
            int h = t >> 3, c2 = (t & 7) * 2;
            *(float4*)&iS[h][c2] = *(const float4*)&g_p[h * Nn + i0 + c2];
        } else {
            int k   = t - 1024;
            int sel = k >> 9;                  // 0 = Ej, 1 = Ei
            int m   = k & 511;
            int h   = m >> 2, c4 = (m & 3) * 4;
            if (sel) *(float4*)&biS[h][c4] = *(const float4*)&g_ei[h * Nn + j0 + c4];
            else     *(float4*)&bjS[h][c4] = *(const float4*)&g_ej[h * Nn + j0 + c4];
        }
    }
    __syncthreads();

    const int g  = tid >> 6;        // h-group 0..3 (32 h each)
    const int t2 = tid & 63;
    const int ii = t2 >> 2;         // 0..15
    const int jq = (t2 & 3) * 4;    // 0,4,8,12
    const int h0 = g * 32;

    float acc0 = 0.f, acc1 = 0.f, acc2 = 0.f, acc3 = 0.f;
#pragma unroll 8
    for (int hl = 0; hl < 32; hl++) {
        const int H = h0 + hl;
        float2 ai = iS[H][ii];                       // (Ei_i, Ej_i)
        float  w  = w2s[H];
        float4 bj = *(const float4*)&bjS[H][jq];     // Ej_j0..j3
        float4 bi = *(const float4*)&biS[H][jq];     // Ei_j0..j3

        float A, B, D, S;
        A = fmaf(ai.x, bj.x, 1.0f); B = fmaf(bi.x, ai.y, 1.0f);
        D = A * B; S = A + B;
        acc0 = fmaf(w, S * rcp_mufu(D), acc0);

        A = fmaf(ai.x, bj.y, 1.0f); B = fmaf(bi.y, ai.y, 1.0f);
        D = A * B; S = A + B;
        acc1 = fmaf(w, S * rcp_mufu(D), acc1);

        A = fmaf(ai.x, bj.z, 1.0f); B = fmaf(bi.z, ai.y, 1.0f);
        D = A * B; S = A + B;
        acc2 = fmaf(w, S * rcp_mufu(D), acc2);

        A = fmaf(ai.x, bj.w, 1.0f); B = fmaf(bi.w, ai.y, 1.0f);
        D = A * B; S = A + B;
        acc3 = fmaf(w, S * rcp_mufu(D), acc3);
    }

    const int base = ii * TS + jq;
    if (g > 0) {
        red[g - 1][base + 0] = acc0;
        red[g - 1][base + 1] = acc1;
        red[g - 1][base + 2] = acc2;
        red[g - 1][base + 3] = acc3;
    }
    __syncthreads();
    if (g == 0) {
        acc0 += red[0][base + 0] + red[1][base + 0] + red[2][base + 0];
        acc1 += red[0][base + 1] + red[1][base + 1] + red[2][base + 1];
        acc2 += red[0][base + 2] + red[1][base + 2] + red[2][base + 2];
        acc3 += red[0][base + 3] + red[1][base + 3] + red[2][base + 3];

        const float cst = sw2 + b2v;
        float4 o;
        o.x = 2.0f * (cst - acc0);
        o.y = 2.0f * (cst - acc1);
        o.z = 2.0f * (cst - acc2);
        o.w = 2.0f * (cst - acc3);

        const int gi = i0 + ii;
        const int gj = j0 + jq;
        *(float4*)&out[gi * Nn + gj] = o;     // upper tile, coalesced
        out[(gj + 0) * Nn + gi] = o.x;        // mirror
        out[(gj + 1) * Nn + gi] = o.y;
        out[(gj + 2) * Nn + gi] = o.z;
        out[(gj + 3) * Nn + gi] = o.w;
    }
}

extern "C" void kernel_launch(void* const* d_in, const int* in_sizes, int n_in,
                              void* d_out, int out_size) {
    const float* x  = (const float*)d_in[0];
    const float* W1 = (const float*)d_in[1];
    const float* b1 = (const float*)d_in[2];
    const float* W2 = (const float*)d_in[3];
    const float* b2 = (const float*)d_in[4];
    float* out = (float*)d_out;

    prep_kernel<<<dim3(32, 4), 256>>>(x, W1, b1, W2);

    cudaLaunchConfig_t cfg = {};
    cfg.gridDim  = dim3(NUNITS);
    cfg.blockDim = dim3(256);
    cfg.dynamicSmemBytes = 0;
    cfg.stream = 0;
    cudaLaunchAttribute attr[1];
    attr[0].id = cudaLaunchAttributeProgrammaticStreamSerialization;
    attr[0].val.programmaticStreamSerializationAllowed = 1;
    cfg.attrs = attr;
    cfg.numAttrs = 1;
    cudaLaunchKernelEx(&cfg, pair_kernel, W2, b2, (float*)out);
}

// round 17
// speedup vs baseline: 1.0027x; 1.0020x over previous
#include <cuda_runtime.h>

#define Nn   1024
#define Cc   64
#define HID  128
#define TS   16
#define NTS  (Nn / TS)                  // 64
#define NUNITS (NTS * (NTS + 1) / 2)    // 2080
#define PNCH 32

__device__ float2 g_p [HID * Nn];       // (Ei, Ej) interleaved (i-side)
__device__ float  g_ei[HID * Nn];       // Ei deinterleaved (j-side)
__device__ float  g_ej[HID * Nn];       // Ej deinterleaved (j-side)
__device__ float  g_sw2;                // sum of W2

__device__ __forceinline__ float rcp_mufu(float d) {
    float r; asm("rcp.approx.f32 %0, %1;" : "=f"(r) : "f"(d)); return r;
}

// closed-form triangular decode: largest a with a*(2*NTS+1-a)/2 <= bid
__device__ __forceinline__ void tri_decode(int bid, int& a, int& b) {
    const float M = 2.0f * NTS + 1.0f;                     // 129
    float disc = M * M - 8.0f * (float)bid;                // 16641 - 8*bid
    int aa = (int)(0.5f * (M - sqrtf(disc)));
    // integer correction (at most one step either way)
    if ((aa + 1) * (2 * NTS + 1 - (aa + 1)) / 2 <= bid) aa++;
    if (aa * (2 * NTS + 1 - aa) / 2 > bid) aa--;
    a = aa;
    b = aa + (bid - aa * (2 * NTS + 1 - aa) / 2);
}

// ---------------------------------------------------------------------------
// prep: GEMV (precise tanhf) -> E = exp(2*p), clamped; interleaved i-side +
// deinterleaved j-side layouts; block(0,0) reduces sum(W2).
// ---------------------------------------------------------------------------
__global__ __launch_bounds__(256) void prep_kernel(const float* __restrict__ x,
                                                   const float* __restrict__ W1,
                                                   const float* __restrict__ b1,
                                                   const float* __restrict__ W2) {
    __shared__ float t_s[Cc][PNCH];
    const int n0   = blockIdx.x * PNCH;
    const int tid  = threadIdx.x;
    const int lane = tid & 31;
    const int w    = tid >> 5;

    for (int k = tid; k < Cc * PNCH; k += 256) {
        int c = k >> 5, n = k & 31;
        t_s[c][n] = tanhf(x[c * Nn + n0 + n]);
    }
    __syncthreads();

#pragma unroll
    for (int g = 0; g < 4; g++) {
        const int h = blockIdx.y * 32 + w * 4 + g;
        const float bb = b1[h];
        float acci = bb, accj = 0.0f;
#pragma unroll
        for (int c = 0; c < Cc; c++) {
            float wj = W1[h * (2 * Cc) + c];        // warp-uniform broadcast
            float wi = W1[h * (2 * Cc) + Cc + c];
            float t  = t_s[c][lane];
            accj = fmaf(wj, t, accj);
            acci = fmaf(wi, t, acci);
        }
        float Ei = fminf(expf(2.0f * acci), 1e8f);
        float Ej = fminf(expf(2.0f * accj), 1e8f);
        const int n = n0 + lane;
        g_p [h * Nn + n] = make_float2(Ei, Ej);
        g_ei[h * Nn + n] = Ei;
        g_ej[h * Nn + n] = Ej;
    }

    if (blockIdx.x == 0 && blockIdx.y == 0 && tid < 32) {
        float s = 0.0f;
        for (int k = lane; k < HID; k += 32) s += W2[k];
#pragma unroll
        for (int o = 16; o; o >>= 1) s += __shfl_xor_sync(0xffffffffu, s, o);
        if (lane == 0) g_sw2 = s;
    }

    __threadfence();
    __syncthreads();
    asm volatile("griddepcontrol.launch_dependents;" ::: "memory");
}

// ---------------------------------------------------------------------------
// pair: 16x16 triangular unit. 256 threads = 4 h-groups x 64 (16 i x 4 jq).
// Per (h,j): A1 = Ei_i*Ej_j+1 ; B1 = Ei_j*Ej_i+1
//   tanh(pi_i+pj_j)+tanh(pi_j+pj_i) = 2 - 2*(A1+B1)/(A1*B1)
//   acc += w2[h]*(A1+B1)*rcp(A1*B1);  out = 2*(sumW2 + b2 - accTot)
// ---------------------------------------------------------------------------
__global__ __launch_bounds__(256, 6) void pair_kernel(const float* __restrict__ W2,
                                                      const float* __restrict__ b2,
                                                      float* __restrict__ out) {
    __shared__ __align__(16) float2 iS [HID][TS];   // (Ei_i, Ej_i)  16KB
    __shared__ __align__(16) float  bjS[HID][TS];   // Ej at j cols   8KB
    __shared__ __align__(16) float  biS[HID][TS];   // Ei at j cols   8KB
    __shared__ float w2s[HID];
    __shared__ float red[3][TS * TS];               // 3KB

    int a, b;
    tri_decode((int)blockIdx.x, a, b);
    const int i0 = a * TS, j0 = b * TS;

    const int tid = threadIdx.x;
    if (tid < HID) w2s[tid] = W2[tid];
    const float b2v = b2[0];

    asm volatile("griddepcontrol.wait;" ::: "memory");
    const float sw2 = g_sw2;

    // stage: iS 1024 float4; bjS 512 float4; biS 512 float4
    for (int t = tid; t < 2048; t += 256) {
        if (t < 1024) {
            int h = t >> 3, c2 = (t & 7) * 2;
            *(float4*)&iS[h][c2] = *(const float4*)&g_p[h * Nn + i0 + c2];
        } else {
            int k   = t - 1024;
            int sel = k >> 9;                  // 0 = Ej, 1 = Ei
            int m   = k & 511;
            int h   = m >> 2, c4 = (m & 3) * 4;
            if (sel) *(float4*)&biS[h][c4] = *(const float4*)&g_ei[h * Nn + j0 + c4];
            else     *(float4*)&bjS[h][c4] = *(const float4*)&g_ej[h * Nn + j0 + c4];
        }
    }
    __syncthreads();

    const int g  = tid >> 6;        // h-group 0..3 (32 h each)
    const int t2 = tid & 63;
    const int ii = t2 >> 2;         // 0..15
    const int jq = (t2 & 3) * 4;    // 0,4,8,12
    const int h0 = g * 32;

    float acc0 = 0.f, acc1 = 0.f, acc2 = 0.f, acc3 = 0.f;
#pragma unroll 8
    for (int hl = 0; hl < 32; hl++) {
        const int H = h0 + hl;
        float2 ai = iS[H][ii];                       // (Ei_i, Ej_i)
        float  w  = w2s[H];
        float4 bj = *(const float4*)&bjS[H][jq];     // Ej_j0..j3
        float4 bi = *(const float4*)&biS[H][jq];     // Ei_j0..j3

        float A, B, D, S;
        A = fmaf(ai.x, bj.x, 1.0f); B = fmaf(bi.x, ai.y, 1.0f);
        D = A * B; S = A + B;
        acc0 = fmaf(w, S * rcp_mufu(D), acc0);

        A = fmaf(ai.x, bj.y, 1.0f); B = fmaf(bi.y, ai.y, 1.0f);
        D = A * B; S = A + B;
        acc1 = fmaf(w, S * rcp_mufu(D), acc1);

        A = fmaf(ai.x, bj.z, 1.0f); B = fmaf(bi.z, ai.y, 1.0f);
        D = A * B; S = A + B;
        acc2 = fmaf(w, S * rcp_mufu(D), acc2);

        A = fmaf(ai.x, bj.w, 1.0f); B = fmaf(bi.w, ai.y, 1.0f);
        D = A * B; S = A + B;
        acc3 = fmaf(w, S * rcp_mufu(D), acc3);
    }

    const int base = ii * TS + jq;
    if (g > 0) {
        red[g - 1][base + 0] = acc0;
        red[g - 1][base + 1] = acc1;
        red[g - 1][base + 2] = acc2;
        red[g - 1][base + 3] = acc3;
    }
    __syncthreads();
    if (g == 0) {
        acc0 += red[0][base + 0] + red[1][base + 0] + red[2][base + 0];
        acc1 += red[0][base + 1] + red[1][base + 1] + red[2][base + 1];
        acc2 += red[0][base + 2] + red[1][base + 2] + red[2][base + 2];
        acc3 += red[0][base + 3] + red[1][base + 3] + red[2][base + 3];

        const float cst = sw2 + b2v;
        float4 o;
        o.x = 2.0f * (cst - acc0);
        o.y = 2.0f * (cst - acc1);
        o.z = 2.0f * (cst - acc2);
        o.w = 2.0f * (cst - acc3);

        const int gi = i0 + ii;
        const int gj = j0 + jq;
        *(float4*)&out[gi * Nn + gj] = o;     // upper tile, coalesced
        out[(gj + 0) * Nn + gi] = o.x;        // mirror
        out[(gj + 1) * Nn + gi] = o.y;
        out[(gj + 2) * Nn + gi] = o.z;
        out[(gj + 3) * Nn + gi] = o.w;
    }
}

extern "C" void kernel_launch(void* const* d_in, const int* in_sizes, int n_in,
                              void* d_out, int out_size) {
    const float* x  = (const float*)d_in[0];
    const float* W1 = (const float*)d_in[1];
    const float* b1 = (const float*)d_in[2];
    const float* W2 = (const float*)d_in[3];
    const float* b2 = (const float*)d_in[4];
    float* out = (float*)d_out;

    prep_kernel<<<dim3(32, 4), 256>>>(x, W1, b1, W2);

    cudaLaunchConfig_t cfg = {};
    cfg.gridDim  = dim3(NUNITS);
    cfg.blockDim = dim3(256);
    cfg.dynamicSmemBytes = 0;
    cfg.stream = 0;
    cudaLaunchAttribute attr[1];
    attr[0].id = cudaLaunchAttributeProgrammaticStreamSerialization;
    attr[0].val.programmaticStreamSerializationAllowed = 1;
    cfg.attrs = attr;
    cfg.numAttrs = 1;
    cudaLaunchKernelEx(&cfg, pair_kernel, W2, b2, (float*)out);
}